// round 10
// baseline (speedup 1.0000x reference)
#include <cuda_runtime.h>
#include <cuda_bf16.h>
#include <cstdint>

#define MAXN 100000
#define MAXE 1600000
#define HIDD 128
#define MAXG 512
#define BN_EPS 1e-5f

// ---------------- scratch (static device globals; no allocations) ------------
__device__ float g_h  [(size_t)MAXN * HIDD];
__device__ float g_m  [(size_t)MAXN * HIDD];
__device__ float g_p  [(size_t)MAXN * HIDD];
__device__ float g_pool[(size_t)MAXG * 3 * HIDD];
__device__ float g_cnt [MAXG];
__device__ float g_stats[2 * HIDD];
__device__ float g_scale2[3 * HIDD];
__device__ float g_shift2[3 * HIDD];
__device__ float g_emb [100 * HIDD];
// packed weights, fragment-pair layout: plane word idx = kc*1024 + col*8 + t*2 + p
#define W_PLANE 8192
__device__ uint32_t g_wpack[6][2][W_PLANE];
// CSR scratch
__device__ int g_deg [MAXN];
__device__ int g_off [MAXN];
__device__ int g_cur [MAXN];
__device__ int g_bsum[256];
__device__ int g_csr [MAXE];

// smem: Ahi[64*72], Alo[64*72], Whi[4096], Wlo[4096]  (words) = 68KB
#define A_STRIDE 72
#define A_PLANE (64 * A_STRIDE)
#define W_SLICE 4096
#define SMEM_BYTES ((2 * A_PLANE + 2 * W_SLICE) * 4)   // 69632

// pair two consecutive-k values into one b16x2 word (low = even k)
__device__ __forceinline__ uint32_t hi_pair(float a, float b)
{
    return (__float_as_uint(a) >> 16) | (__float_as_uint(b) & 0xFFFF0000u);
}
__device__ __forceinline__ uint32_t lo_pair(float a, float b)
{
    float ra = a - __uint_as_float(__float_as_uint(a) & 0xFFFF0000u);
    float rb = b - __uint_as_float(__float_as_uint(b) & 0xFFFF0000u);
    uint32_t la = (uint32_t)__bfloat16_as_ushort(__float2bfloat16(ra));
    uint32_t lb = (uint32_t)__bfloat16_as_ushort(__float2bfloat16(rb));
    return la | (lb << 16);
}

__device__ __forceinline__ void mma_bf16(float c[4], const uint32_t a[4], const uint32_t b[2])
{
    asm volatile(
        "mma.sync.aligned.m16n8k16.row.col.f32.bf16.bf16.f32 "
        "{%0,%1,%2,%3}, {%4,%5,%6,%7}, {%8,%9}, {%0,%1,%2,%3};"
        : "+f"(c[0]), "+f"(c[1]), "+f"(c[2]), "+f"(c[3])
        : "r"(a[0]), "r"(a[1]), "r"(a[2]), "r"(a[3]), "r"(b[0]), "r"(b[1]));
}

// ---------------- bf16x3 tensor-core GEMM: out = f(A)[n,128] @ Wpack[widx] ---
// 64x64 tiles (gridDim.y=2 over N), 3 CTAs/SM, split hh/mix accumulator chains.
__global__ void __launch_bounds__(256, 3)
gemm_mma(const float* __restrict__ A, int widx,
         const float* __restrict__ bias, const int* __restrict__ z,
         const float* __restrict__ bnsc, const float* __restrict__ bnsh,
         float* __restrict__ out, int n, int do_relu, int do_stats, int do_emb,
         const int* __restrict__ batch, float* __restrict__ pool, int loff, int do_pool)
{
    extern __shared__ uint32_t sh[];
    uint32_t* Ahi = sh;
    uint32_t* Alo = sh + A_PLANE;
    uint32_t* Whi = sh + 2 * A_PLANE;
    uint32_t* Wlo = sh + 2 * A_PLANE + W_SLICE;
    const int tid    = threadIdx.x;          // 256
    const int row0   = blockIdx.x * 64;
    const int coloff = blockIdx.y * 64;      // N-slice origin

    // stage W slice: 2 planes x 8 kc x 512 contiguous words
    {
        const int cw = coloff * 8;           // word offset of col slice within kc seg
        for (int idx = tid; idx < 2048; idx += 256) {
            int pl = idx >> 10;              // plane
            int kc = (idx >> 7) & 7;
            int j  = idx & 127;              // uint4 within 512-word run
            uint4 v = *(const uint4*)&g_wpack[widx][pl][kc * 1024 + cw + j * 4];
            *(uint4*)&sh[2 * A_PLANE + pl * W_SLICE + kc * 512 + j * 4] = v;
        }
    }
    // stage A into fragment-pair layout, optional BN affine
    for (int i = tid; i < 2048; i += 256) {
        int r  = i >> 5;                 // 0..63
        int c4 = (i & 31) * 4;           // k = c4..c4+3
        int row = row0 + r;
        float4 v = make_float4(0.f, 0.f, 0.f, 0.f);
        if (row < n) v = *(const float4*)&A[(size_t)row * 128 + c4];
        if (bnsc) {
            v.x = v.x * bnsc[c4 + 0] + bnsh[c4 + 0];
            v.y = v.y * bnsc[c4 + 1] + bnsh[c4 + 1];
            v.z = v.z * bnsc[c4 + 2] + bnsh[c4 + 2];
            v.w = v.w * bnsc[c4 + 3] + bnsh[c4 + 3];
        }
        int kh0 = (i & 31) * 2, kh1 = kh0 + 1;
        int p0 = r * A_STRIDE + ((kh0 >> 3) << 3) + (kh0 & 3) * 2 + ((kh0 >> 2) & 1);
        int p1 = r * A_STRIDE + ((kh1 >> 3) << 3) + (kh1 & 3) * 2 + ((kh1 >> 2) & 1);
        Ahi[p0] = hi_pair(v.x, v.y);
        Ahi[p1] = hi_pair(v.z, v.w);
        Alo[p0] = lo_pair(v.x, v.y);
        Alo[p1] = lo_pair(v.z, v.w);
    }
    __syncthreads();

    const int w    = tid >> 5;
    const int lane = tid & 31;
    const int wm0  = (w & 3) * 16;       // 4 warps in M (16 rows each)
    const int n0   = (w >> 2) * 32;      // 2 warps in N (32 cols each, within slice)
    const int g    = lane >> 2;
    const int t    = lane & 3;

    float chh[4][4], cmx[4][4];
    #pragma unroll
    for (int nt = 0; nt < 4; nt++)
        #pragma unroll
        for (int j = 0; j < 4; j++) { chh[nt][j] = 0.f; cmx[nt][j] = 0.f; }

    const int abase = (wm0 + g) * A_STRIDE + 2 * t;
    const int wbase = (n0 + g) * 8 + 2 * t;

    #pragma unroll
    for (int kc = 0; kc < 8; kc++) {
        int ab = abase + kc * 8;
        uint2 Ah0 = *(uint2*)&Ahi[ab];
        uint2 Ah1 = *(uint2*)&Ahi[ab + 8 * A_STRIDE];
        uint2 Al0 = *(uint2*)&Alo[ab];
        uint2 Al1 = *(uint2*)&Alo[ab + 8 * A_STRIDE];
        uint32_t ahi[4] = {Ah0.x, Ah1.x, Ah0.y, Ah1.y};
        uint32_t alo[4] = {Al0.x, Al1.x, Al0.y, Al1.y};
        int wb = wbase + kc * 512;
        #pragma unroll
        for (int nt = 0; nt < 4; nt++) {
            uint2 Bh = *(uint2*)&Whi[wb + nt * 64];
            uint2 Bl = *(uint2*)&Wlo[wb + nt * 64];
            uint32_t bhi[2] = {Bh.x, Bh.y};
            uint32_t blo[2] = {Bl.x, Bl.y};
            mma_bf16(chh[nt], ahi, bhi);   // hi*hi   (independent chain)
            mma_bf16(cmx[nt], ahi, blo);   // hi*lo   (mix chain)
            mma_bf16(cmx[nt], alo, bhi);   // lo*hi
        }
    }

    // ---------------- epilogue ----------------
    float sst[8], qst[8];
    #pragma unroll
    for (int i = 0; i < 8; i++) { sst[i] = 0.f; qst[i] = 0.f; }

    #pragma unroll
    for (int rr = 0; rr < 2; rr++) {
        int row = row0 + wm0 + rr * 8 + g;
        bool valid = row < n;
        const float* er = nullptr;
        if (do_emb && valid) er = &g_emb[(size_t)z[row] * 128];
        float* prow = nullptr;
        if (do_pool && valid) prow = &pool[(size_t)batch[row] * 384 + loff];
        #pragma unroll
        for (int nt = 0; nt < 4; nt++) {
            int col0 = coloff + n0 + nt * 8 + 2 * t;
            float v0 = chh[nt][rr * 2 + 0] + cmx[nt][rr * 2 + 0];
            float v1 = chh[nt][rr * 2 + 1] + cmx[nt][rr * 2 + 1];
            if (bias) { v0 += bias[col0]; v1 += bias[col0 + 1]; }
            if (er)   { v0 += er[col0];   v1 += er[col0 + 1]; }
            if (do_relu) { v0 = fmaxf(v0, 0.f); v1 = fmaxf(v1, 0.f); }
            if (do_stats && valid) {
                sst[nt * 2 + 0] += v0; qst[nt * 2 + 0] += v0 * v0;
                sst[nt * 2 + 1] += v1; qst[nt * 2 + 1] += v1 * v1;
            }
            if (valid) {
                *(float2*)&out[(size_t)row * 128 + col0] = make_float2(v0, v1);
                if (prow)
                    asm volatile("red.global.add.v2.f32 [%0], {%1,%2};"
                                 :: "l"(prow + col0), "f"(v0), "f"(v1) : "memory");
            }
        }
    }

    if (do_stats) {
        #pragma unroll
        for (int i = 0; i < 8; i++) {
            #pragma unroll
            for (int msk = 4; msk < 32; msk <<= 1) {
                sst[i] += __shfl_xor_sync(0xffffffffu, sst[i], msk);
                qst[i] += __shfl_xor_sync(0xffffffffu, qst[i], msk);
            }
        }
        if (g == 0) {
            #pragma unroll
            for (int i = 0; i < 8; i++) {
                int col = coloff + n0 + (i >> 1) * 8 + 2 * t + (i & 1);
                atomicAdd(&g_stats[col], sst[i]);
                atomicAdd(&g_stats[128 + col], qst[i]);
            }
        }
    }
}

// ---------------- prep: embsum + pack all 6 weight matrices ------------------
__global__ void prep_k(const float* __restrict__ W0, const float* __restrict__ W1,
                       const float* __restrict__ W2, const float* __restrict__ W3,
                       const float* __restrict__ W4, const float* __restrict__ W5,
                       const float* __restrict__ W1_0full)
{
    int b = blockIdx.x;
    if (b < 50) {
        int zi = b * 2 + (threadIdx.x >> 7);
        int c  = threadIdx.x & 127;
        g_emb[zi * 128 + c] = W1_0full[zi * 128 + c] + W1_0full[(100 + zi) * 128 + c];
        return;
    }
    int widx = (b - 50) >> 3;
    int blk  = (b - 50) & 7;
    const float* W = W0;
    if (widx == 1) W = W1; else if (widx == 2) W = W2;
    else if (widx == 3) W = W3; else if (widx == 4) W = W4;
    else if (widx == 5) W = W5;
    int i  = blk * 256 + threadIdx.x;    // 0..2047
    int kh = i >> 5;
    int c4 = (i & 31) * 4;
    float4 r0 = *(const float4*)&W[(2 * kh)     * 128 + c4];
    float4 r1 = *(const float4*)&W[(2 * kh + 1) * 128 + c4];
    int kc = kh >> 3, t = kh & 3, p = (kh >> 2) & 1;
    int base = kc * 1024 + t * 2 + p;
    float h[4] = {r0.x, r0.y, r0.z, r0.w};
    float l[4] = {r1.x, r1.y, r1.z, r1.w};
    #pragma unroll
    for (int j = 0; j < 4; j++) {
        int pos = base + (c4 + j) * 8;
        g_wpack[widx][0][pos] = hi_pair(h[j], l[j]);
        g_wpack[widx][1][pos] = lo_pair(h[j], l[j]);
    }
}

// ---------------- CSR build --------------------------------------------------
__global__ void hist_k(const int* __restrict__ ei, int E)
{
    int e = blockIdx.x * blockDim.x + threadIdx.x;
    if (e < E) atomicAdd(&g_deg[ei[E + e]], 1);
}

__global__ void scan1_k(int n)
{
    __shared__ int s[1024];
    int t = threadIdx.x, i = blockIdx.x * 1024 + t;
    int v = (i < n) ? g_deg[i] : 0;
    s[t] = v;
    __syncthreads();
    #pragma unroll
    for (int d = 1; d < 1024; d <<= 1) {
        int x = (t >= d) ? s[t - d] : 0;
        __syncthreads();
        s[t] += x;
        __syncthreads();
    }
    if (i < n) g_off[i] = s[t] - v;
    if (t == 1023) g_bsum[blockIdx.x] = s[t];
}

__global__ void scan2_k(int nb)
{
    __shared__ int s[256];
    int t = threadIdx.x;
    int v = (t < nb) ? g_bsum[t] : 0;
    s[t] = v;
    __syncthreads();
    #pragma unroll
    for (int d = 1; d < 256; d <<= 1) {
        int x = (t >= d) ? s[t - d] : 0;
        __syncthreads();
        s[t] += x;
        __syncthreads();
    }
    if (t < nb) g_bsum[t] = s[t] - v;
}

__global__ void scan3_k(int n)
{
    int i = blockIdx.x * blockDim.x + threadIdx.x;
    if (i < n) g_off[i] += g_bsum[i >> 10];
}

__global__ void scatter_k(const int* __restrict__ ei, int E)
{
    int e = blockIdx.x * blockDim.x + threadIdx.x;
    if (e >= E) return;
    int dst = ei[E + e];
    int pos = g_off[dst] + atomicAdd(&g_cur[dst], 1);
    g_csr[pos] = ei[e];
}

// ---------------- fused aggregation: m = relu(p + sum_csr p[src] + b1) -------
__global__ void agg_fused(const float* __restrict__ p, const float* __restrict__ b,
                          float* __restrict__ out, int n)
{
    int w    = (blockIdx.x * blockDim.x + threadIdx.x) >> 5;
    int lane = threadIdx.x & 31;
    if (w >= n) return;
    int off = g_off[w], deg = g_deg[w];
    const float* pc = p + (size_t)lane * 4;
    float4 acc = *(const float4*)&pc[(size_t)w * 128];

    for (int base = 0; base < deg; base += 32) {
        int idx = 0;
        if (base + lane < deg) idx = g_csr[off + base + lane];
        int cnt = min(32, deg - base);
        int j = 0;
        for (; j + 4 <= cnt; j += 4) {
            int s0 = __shfl_sync(0xffffffffu, idx, j);
            int s1 = __shfl_sync(0xffffffffu, idx, j + 1);
            int s2 = __shfl_sync(0xffffffffu, idx, j + 2);
            int s3 = __shfl_sync(0xffffffffu, idx, j + 3);
            float4 v0 = *(const float4*)&pc[(size_t)s0 * 128];
            float4 v1 = *(const float4*)&pc[(size_t)s1 * 128];
            float4 v2 = *(const float4*)&pc[(size_t)s2 * 128];
            float4 v3 = *(const float4*)&pc[(size_t)s3 * 128];
            acc.x += v0.x + v1.x + v2.x + v3.x;
            acc.y += v0.y + v1.y + v2.y + v3.y;
            acc.z += v0.z + v1.z + v2.z + v3.z;
            acc.w += v0.w + v1.w + v2.w + v3.w;
        }
        for (; j < cnt; j++) {
            int s = __shfl_sync(0xffffffffu, idx, j);
            float4 v = *(const float4*)&pc[(size_t)s * 128];
            acc.x += v.x; acc.y += v.y; acc.z += v.z; acc.w += v.w;
        }
    }
    float4 bv = *(const float4*)&b[lane * 4];
    float4 o;
    o.x = fmaxf(acc.x + bv.x, 0.f);
    o.y = fmaxf(acc.y + bv.y, 0.f);
    o.z = fmaxf(acc.z + bv.z, 0.f);
    o.w = fmaxf(acc.w + bv.w, 0.f);
    *(float4*)&out[(size_t)w * 128 + lane * 4] = o;
}

// ---------------- per-graph node counts --------------------------------------
__global__ void count_k(const int* __restrict__ batch, float* __restrict__ cnt, int n)
{
    int i = blockIdx.x * blockDim.x + threadIdx.x;
    if (i < n) atomicAdd(&cnt[batch[i]], 1.0f);
}

// ---------------- BN coefficients from stats (per layer) ---------------------
__global__ void bn_coef(const float* __restrict__ gamma, const float* __restrict__ beta,
                        int n, int l)
{
    int c = threadIdx.x;
    float invn = 1.0f / (float)n;
    float mu   = g_stats[c] * invn;
    float var  = g_stats[128 + c] * invn - mu * mu;
    float rstd = rsqrtf(var + BN_EPS);
    float sc   = gamma[c] * rstd;
    g_scale2[l * 128 + c] = sc;
    g_shift2[l * 128 + c] = beta[c] - mu * sc;
}

// ---------------- final head (applies linear-pool BN correction) -------------
__global__ void final_mlp(const float* __restrict__ Wl1, const float* __restrict__ bl1,
                          const float* __restrict__ Wl2, const float* __restrict__ bl2,
                          float* __restrict__ out)
{
    int g = blockIdx.x, tid = threadIdx.x;
    __shared__ float pooled[384];
    float cntv = g_cnt[g];
    float ic   = 1.0f / fmaxf(cntv, 1.0f);
    float have = cntv * ic;
    for (int i = tid; i < 384; i += 128)
        pooled[i] = g_pool[(size_t)g * 384 + i] * g_scale2[i] * ic + g_shift2[i] * have;
    __syncthreads();
    float a = bl1[tid];
    #pragma unroll 4
    for (int k = 0; k < 384; k++)
        a = fmaf(pooled[k], Wl1[k * 128 + tid], a);
    float v = fmaxf(a, 0.f) * Wl2[tid];
    #pragma unroll
    for (int o = 16; o; o >>= 1) v += __shfl_xor_sync(0xffffffffu, v, o);
    __shared__ float ws[4];
    if ((tid & 31) == 0) ws[tid >> 5] = v;
    __syncthreads();
    if (tid == 0) out[g] = ws[0] + ws[1] + ws[2] + ws[3] + bl2[0];
}

// -----------------------------------------------------------------------------
extern "C" void kernel_launch(void* const* d_in, const int* in_sizes, int n_in,
                              void* d_out, int out_size)
{
    const float* x     = (const float*)d_in[0];
    const int*   z     = (const int*)  d_in[1];
    const int*   ei    = (const int*)  d_in[2];
    const int*   batch = (const int*)  d_in[3];
    const float *W1[3], *b1[3], *W2[3], *b2[3], *ga[3], *be[3];
    for (int l = 0; l < 3; l++) {
        W1[l] = (const float*)d_in[4 + 6 * l];
        b1[l] = (const float*)d_in[5 + 6 * l];
        W2[l] = (const float*)d_in[6 + 6 * l];
        b2[l] = (const float*)d_in[7 + 6 * l];
        ga[l] = (const float*)d_in[8 + 6 * l];
        be[l] = (const float*)d_in[9 + 6 * l];
    }
    const float* Wl1 = (const float*)d_in[22];
    const float* bl1 = (const float*)d_in[23];
    const float* Wl2 = (const float*)d_in[24];
    const float* bl2 = (const float*)d_in[25];
    float* out = (float*)d_out;

    int n = in_sizes[0] / 128;
    int E = in_sizes[2] / 2;
    int G = out_size;

    float *p_h, *p_m, *p_p, *p_pool, *p_cnt, *p_stats, *p_scale2, *p_shift2;
    int *p_deg, *p_cur;
    cudaGetSymbolAddress((void**)&p_h,      g_h);
    cudaGetSymbolAddress((void**)&p_m,      g_m);
    cudaGetSymbolAddress((void**)&p_p,      g_p);
    cudaGetSymbolAddress((void**)&p_pool,   g_pool);
    cudaGetSymbolAddress((void**)&p_cnt,    g_cnt);
    cudaGetSymbolAddress((void**)&p_stats,  g_stats);
    cudaGetSymbolAddress((void**)&p_scale2, g_scale2);
    cudaGetSymbolAddress((void**)&p_shift2, g_shift2);
    cudaGetSymbolAddress((void**)&p_deg,    g_deg);
    cudaGetSymbolAddress((void**)&p_cur,    g_cur);

    cudaFuncSetAttribute(gemm_mma, cudaFuncAttributeMaxDynamicSharedMemorySize, SMEM_BYTES);

    dim3 ggrid((n + 63) / 64, 2);
    size_t tot32 = (size_t)n * 32;
    int    nb32  = (int)((tot32 + 255) / 256);
    int    nb_scan = (n + 1023) / 1024;

    // ---- setup (same launch-prefix count: gemm is launch #8) -----------------
    cudaMemsetAsync(p_pool, 0, (size_t)G * 384 * sizeof(float));   // 1
    cudaMemsetAsync(p_cnt,  0, (size_t)G * sizeof(float));         // 2
    cudaMemsetAsync(p_deg,  0, (size_t)n * sizeof(int));           // 3
    cudaMemsetAsync(p_cur,  0, (size_t)n * sizeof(int));           // 4
    count_k<<<(n + 255) / 256, 256>>>(batch, p_cnt, n);            // 5
    prep_k<<<98, 256>>>(W1[0] + 200 * 128, W2[0], W1[1], W2[1],    // 6
                        W1[2], W2[2], W1[0]);
    hist_k<<<(E + 255) / 256, 256>>>(ei, E);                       // 7

    // layer-0 GEMM1: p = x @ W1_0[200:] + embsum[z]                // 8
    gemm_mma<<<ggrid, 256, SMEM_BYTES>>>(x, 0, nullptr, z,
                                         nullptr, nullptr, p_h, n, 0, 0, 1,
                                         nullptr, nullptr, 0, 0);

    scan1_k  <<<nb_scan, 1024>>>(n);
    scan2_k  <<<1, 256>>>(nb_scan);
    scan3_k  <<<(n + 255) / 256, 256>>>(n);
    scatter_k<<<(E + 255) / 256, 256>>>(ei, E);

    for (int l = 0; l < 3; l++) {
        if (l > 0)
            gemm_mma<<<ggrid, 256, SMEM_BYTES>>>(p_p, 2 * l, nullptr, nullptr,
                                                 p_scale2 + (l - 1) * 128,
                                                 p_shift2 + (l - 1) * 128,
                                                 p_h, n, 0, 0, 0,
                                                 nullptr, nullptr, 0, 0);

        // m = relu(p + sum_{src->i} p[src] + b1)
        agg_fused<<<nb32, 256>>>(p_h, b1[l], p_m, n);

        // t = relu(m @ W2 + b2), fused BN-stats + raw pooled-sum accumulation
        cudaMemsetAsync(p_stats, 0, 256 * sizeof(float));
        gemm_mma<<<ggrid, 256, SMEM_BYTES>>>(p_m, 2 * l + 1, b2[l], nullptr,
                                             nullptr, nullptr, p_p, n, 1, 1, 0,
                                             batch, p_pool, l * 128, 1);

        bn_coef<<<1, 128>>>(ga[l], be[l], n, l);
    }

    final_mlp<<<G, 128>>>(Wl1, bl1, Wl2, bl2, out);
}

// round 12
// speedup vs baseline: 1.2699x; 1.2699x over previous
#include <cuda_runtime.h>
#include <cuda_bf16.h>
#include <cstdint>

#define MAXN 100000
#define MAXE 1600000
#define MAXG 512
#define BN_EPS 1e-5f
#define NPLANE ((size_t)MAXN * 64)

// ---------------- scratch (static device globals; no allocations) ------------
__device__ float    g_h [(size_t)MAXN * 128];   // fp32 p (GEMM1 out, agg in)
__device__ uint32_t g_m [(size_t)MAXN * 128];   // packed m planes (agg out)
__device__ uint32_t g_p [(size_t)MAXN * 128];   // packed t planes (GEMM2 out)
__device__ float g_pool[(size_t)MAXG * 384];
__device__ float g_cnt [MAXG];
__device__ float g_stats[256];
__device__ float g_scale2[384];
__device__ float g_shift2[384];
__device__ float g_emb [100 * 128];
__device__ float g_brow[128];
// packed weights: layout word (kh, c) at kh*136 + c  (kh pairs rows 2kh,2kh+1)
#define WS2 136
#define W_PLANE (64 * WS2)
__device__ uint32_t g_wpack[6][2][W_PLANE];
// CSR scratch
__device__ int g_deg [MAXN];
__device__ int g_off [MAXN];
__device__ int g_bsum[256];
__device__ int g_csr [MAXE];

// smem: Ahi[128][68], Alo[128][68], Whi[64][136], Wlo[64][136]
#define AS2 68
#define A_PLANE (128 * AS2)
#define SMEM_BYTES ((2 * A_PLANE + 2 * W_PLANE) * 4)   // 139264

// pair two consecutive-k values into one b16x2 word (low = even k)
__device__ __forceinline__ uint32_t hi_pair(float a, float b)
{
    return (__float_as_uint(a) >> 16) | (__float_as_uint(b) & 0xFFFF0000u);
}
__device__ __forceinline__ uint32_t lo_pair(float a, float b)
{
    float ra = a - __uint_as_float(__float_as_uint(a) & 0xFFFF0000u);
    float rb = b - __uint_as_float(__float_as_uint(b) & 0xFFFF0000u);
    uint32_t la = (uint32_t)__bfloat16_as_ushort(__float2bfloat16(ra));
    uint32_t lb = (uint32_t)__bfloat16_as_ushort(__float2bfloat16(rb));
    return la | (lb << 16);
}

__device__ __forceinline__ void mma_bf16(float c[4], const uint32_t a[4], const uint32_t b[2])
{
    asm volatile(
        "mma.sync.aligned.m16n8k16.row.col.f32.bf16.bf16.f32 "
        "{%0,%1,%2,%3}, {%4,%5,%6,%7}, {%8,%9}, {%0,%1,%2,%3};"
        : "+f"(c[0]), "+f"(c[1]), "+f"(c[2]), "+f"(c[3])
        : "r"(a[0]), "r"(a[1]), "r"(a[2]), "r"(a[3]), "r"(b[0]), "r"(b[1]));
}

// ---------------- bf16x3 tensor-core GEMM: 128x128 tiles, 1 CTA/SM -----------
// A: fp32 (packs inline) or pre-packed planes (straight copy).
// out_mode: 0 = fp32 store, 1 = packed store, 2 = no store.
__global__ void __launch_bounds__(256, 1)
gemm_mma(const float* __restrict__ A, const uint32_t* __restrict__ Apack, int widx,
         const float* __restrict__ bias, const int* __restrict__ z, int do_emb,
         float* __restrict__ outf, uint32_t* __restrict__ outp, int out_mode,
         int n, int do_relu, int do_stats,
         const int* __restrict__ batch, float* __restrict__ pool, int loff, int do_pool)
{
    extern __shared__ uint32_t sh[];
    uint32_t* Ahi = sh;
    uint32_t* Alo = sh + A_PLANE;
    uint32_t* Whi = sh + 2 * A_PLANE;
    uint32_t* Wlo = sh + 2 * A_PLANE + W_PLANE;
    const int tid  = threadIdx.x;            // 256
    const int row0 = blockIdx.x * 128;

    // stage W: straight uint4 copy of pre-packed planes
    {
        const uint4* src = (const uint4*)&g_wpack[widx][0][0];
        uint4* dst = (uint4*)Whi;
        for (int i = tid; i < (2 * W_PLANE) / 4; i += 256)
            dst[i] = src[i];
    }
    // stage A
    if (Apack) {
        for (int i = tid; i < 4096; i += 256) {
            int r  = i >> 5;                  // 0..127
            int jw = (i & 31) * 2;            // word pair index 0..62
            int row = row0 + r;
            uint2 hv = make_uint2(0u, 0u), lv = make_uint2(0u, 0u);
            if (row < n) {
                hv = *(const uint2*)&Apack[(size_t)row * 64 + jw];
                lv = *(const uint2*)&Apack[NPLANE + (size_t)row * 64 + jw];
            }
            *(uint2*)&Ahi[r * AS2 + jw] = hv;
            *(uint2*)&Alo[r * AS2 + jw] = lv;
        }
    } else {
        for (int i = tid; i < 4096; i += 256) {
            int r  = i >> 5;
            int c4 = (i & 31) * 4;
            int row = row0 + r;
            float4 v = make_float4(0.f, 0.f, 0.f, 0.f);
            if (row < n) v = *(const float4*)&A[(size_t)row * 128 + c4];
            uint2 hv, lv;
            hv.x = hi_pair(v.x, v.y); lv.x = lo_pair(v.x, v.y);
            hv.y = hi_pair(v.z, v.w); lv.y = lo_pair(v.z, v.w);
            *(uint2*)&Ahi[r * AS2 + (c4 >> 1)] = hv;
            *(uint2*)&Alo[r * AS2 + (c4 >> 1)] = lv;
        }
    }
    __syncthreads();

    const int w    = tid >> 5;
    const int lane = tid & 31;
    const int wm0  = (w & 3) * 32;       // 4 warps in M (32 rows each)
    const int n0   = (w >> 2) * 64;      // 2 warps in N (64 cols each)
    const int g    = lane >> 2;
    const int t    = lane & 3;

    float c[2][8][4];
    #pragma unroll
    for (int mt = 0; mt < 2; mt++)
        #pragma unroll
        for (int nt = 0; nt < 8; nt++)
            #pragma unroll
            for (int j = 0; j < 4; j++) c[mt][nt][j] = 0.f;

    #pragma unroll
    for (int kc = 0; kc < 8; kc++) {
        int kh16 = kc * 8;
        uint32_t ahi[2][4], alo[2][4];
        #pragma unroll
        for (int mt = 0; mt < 2; mt++) {
            int base = (wm0 + mt * 16 + g) * AS2 + kh16 + t;
            ahi[mt][0] = Ahi[base];
            ahi[mt][1] = Ahi[base + 8 * AS2];
            ahi[mt][2] = Ahi[base + 4];
            ahi[mt][3] = Ahi[base + 4 + 8 * AS2];
            alo[mt][0] = Alo[base];
            alo[mt][1] = Alo[base + 8 * AS2];
            alo[mt][2] = Alo[base + 4];
            alo[mt][3] = Alo[base + 4 + 8 * AS2];
        }
        #pragma unroll
        for (int nt = 0; nt < 8; nt++) {
            int col = n0 + nt * 8 + g;
            int wb  = (kh16 + t) * WS2 + col;
            uint32_t bhi[2], blo[2];
            bhi[0] = Whi[wb];
            bhi[1] = Whi[wb + 4 * WS2];
            blo[0] = Wlo[wb];
            blo[1] = Wlo[wb + 4 * WS2];
            #pragma unroll
            for (int mt = 0; mt < 2; mt++) {
                mma_bf16(c[mt][nt], ahi[mt], bhi);   // hi*hi
                mma_bf16(c[mt][nt], ahi[mt], blo);   // hi*lo
                mma_bf16(c[mt][nt], alo[mt], bhi);   // lo*hi
            }
        }
    }

    // ---------------- epilogue ----------------
    float sst[16], qst[16];
    #pragma unroll
    for (int i = 0; i < 16; i++) { sst[i] = 0.f; qst[i] = 0.f; }

    #pragma unroll
    for (int mt = 0; mt < 2; mt++) {
        #pragma unroll
        for (int rr = 0; rr < 2; rr++) {
            int row = row0 + wm0 + mt * 16 + rr * 8 + g;
            bool valid = row < n;
            const float* er = nullptr;
            if (do_emb && valid) er = &g_emb[(size_t)z[row] * 128];
            float* prow = nullptr;
            if (do_pool && valid) prow = &pool[(size_t)batch[row] * 384 + loff];
            #pragma unroll
            for (int nt = 0; nt < 8; nt++) {
                int col0 = n0 + nt * 8 + 2 * t;
                float v0 = c[mt][nt][rr * 2 + 0];
                float v1 = c[mt][nt][rr * 2 + 1];
                if (bias) { v0 += bias[col0]; v1 += bias[col0 + 1]; }
                if (er)   { v0 += er[col0];   v1 += er[col0 + 1]; }
                if (do_relu) { v0 = fmaxf(v0, 0.f); v1 = fmaxf(v1, 0.f); }
                if (do_stats && valid) {
                    sst[nt * 2 + 0] += v0; qst[nt * 2 + 0] += v0 * v0;
                    sst[nt * 2 + 1] += v1; qst[nt * 2 + 1] += v1 * v1;
                }
                if (valid) {
                    if (out_mode == 0) {
                        *(float2*)&outf[(size_t)row * 128 + col0] = make_float2(v0, v1);
                    } else if (out_mode == 1) {
                        size_t wi = (size_t)row * 64 + (col0 >> 1);
                        outp[wi]          = hi_pair(v0, v1);
                        outp[NPLANE + wi] = lo_pair(v0, v1);
                    }
                    if (prow)
                        asm volatile("red.global.add.v2.f32 [%0], {%1,%2};"
                                     :: "l"(prow + col0), "f"(v0), "f"(v1) : "memory");
                }
            }
        }
    }

    if (do_stats) {
        #pragma unroll
        for (int i = 0; i < 16; i++) {
            #pragma unroll
            for (int msk = 4; msk < 32; msk <<= 1) {
                sst[i] += __shfl_xor_sync(0xffffffffu, sst[i], msk);
                qst[i] += __shfl_xor_sync(0xffffffffu, qst[i], msk);
            }
        }
        if (g == 0) {
            #pragma unroll
            for (int i = 0; i < 16; i++) {
                int col = n0 + (i >> 1) * 8 + 2 * t + (i & 1);
                atomicAdd(&g_stats[col], sst[i]);
                atomicAdd(&g_stats[128 + col], qst[i]);
            }
        }
    }
}

// ---------------- prep: embsum + pack all 6 weight matrices ------------------
// blocks 0..49 = embsum; 50..97 = pack (8 blocks per weight)
__global__ void prep_k(const float* __restrict__ W0, const float* __restrict__ W1,
                       const float* __restrict__ W2, const float* __restrict__ W3,
                       const float* __restrict__ W4, const float* __restrict__ W5,
                       const float* __restrict__ W1_0full)
{
    int b = blockIdx.x;
    if (b < 50) {
        int zi = b * 2 + (threadIdx.x >> 7);
        int c  = threadIdx.x & 127;
        g_emb[zi * 128 + c] = W1_0full[zi * 128 + c] + W1_0full[(100 + zi) * 128 + c];
        return;
    }
    int widx = (b - 50) >> 3;
    int blk  = (b - 50) & 7;
    const float* W = W0;
    if (widx == 1) W = W1; else if (widx == 2) W = W2;
    else if (widx == 3) W = W3; else if (widx == 4) W = W4;
    else if (widx == 5) W = W5;
    int i  = blk * 256 + threadIdx.x;    // 0..2047
    int kh = i >> 5;
    int c4 = (i & 31) * 4;
    float4 r0 = *(const float4*)&W[(2 * kh)     * 128 + c4];
    float4 r1 = *(const float4*)&W[(2 * kh + 1) * 128 + c4];
    uint4 hv, lv;
    hv.x = hi_pair(r0.x, r1.x); lv.x = lo_pair(r0.x, r1.x);
    hv.y = hi_pair(r0.y, r1.y); lv.y = lo_pair(r0.y, r1.y);
    hv.z = hi_pair(r0.z, r1.z); lv.z = lo_pair(r0.z, r1.z);
    hv.w = hi_pair(r0.w, r1.w); lv.w = lo_pair(r0.w, r1.w);
    *(uint4*)&g_wpack[widx][0][kh * WS2 + c4] = hv;
    *(uint4*)&g_wpack[widx][1][kh * WS2 + c4] = lv;
}

// ---------------- weight fold: W1eff = diag(sc)*W1, brow += sh@W1 ------------
__global__ void wfold_k(const float* __restrict__ W1n, const float* __restrict__ sc,
                        const float* __restrict__ shv, int slot)
{
    int idx = blockIdx.x * 256 + threadIdx.x;   // grid 32 -> 8192
    int kh = idx >> 7, c = idx & 127;
    float s0 = sc[2 * kh], s1 = sc[2 * kh + 1];
    float v0 = W1n[(2 * kh) * 128 + c];
    float v1 = W1n[(2 * kh + 1) * 128 + c];
    g_wpack[slot][0][kh * WS2 + c] = hi_pair(s0 * v0, s1 * v1);
    g_wpack[slot][1][kh * WS2 + c] = lo_pair(s0 * v0, s1 * v1);
    atomicAdd(&g_brow[c], shv[2 * kh] * v0 + shv[2 * kh + 1] * v1);
}

// ---------------- hist (edge degrees) + per-graph node counts ----------------
__global__ void hist_count_k(const int* __restrict__ ei, const int* __restrict__ batch,
                             int E, int n)
{
    int idx = blockIdx.x * blockDim.x + threadIdx.x;
    if (idx < E) atomicAdd(&g_deg[ei[E + idx]], 1);
    if (idx < n) atomicAdd(&g_cnt[batch[idx]], 1.0f);
}

// ---------------- CSR scans + scatter ----------------------------------------
__global__ void scan1_k(int n)
{
    __shared__ int s[1024];
    int t = threadIdx.x, i = blockIdx.x * 1024 + t;
    int v = (i < n) ? g_deg[i] : 0;
    s[t] = v;
    __syncthreads();
    #pragma unroll
    for (int d = 1; d < 1024; d <<= 1) {
        int x = (t >= d) ? s[t - d] : 0;
        __syncthreads();
        s[t] += x;
        __syncthreads();
    }
    if (i < n) g_off[i] = s[t] - v;
    if (t == 1023) g_bsum[blockIdx.x] = s[t];
}

__global__ void scan2_k(int nb)
{
    __shared__ int s[256];
    int t = threadIdx.x;
    int v = (t < nb) ? g_bsum[t] : 0;
    s[t] = v;
    __syncthreads();
    #pragma unroll
    for (int d = 1; d < 256; d <<= 1) {
        int x = (t >= d) ? s[t - d] : 0;
        __syncthreads();
        s[t] += x;
        __syncthreads();
    }
    if (t < nb) g_bsum[t] = s[t] - v;
}

__global__ void scan3_k(int n)
{
    int i = blockIdx.x * blockDim.x + threadIdx.x;
    if (i < n) g_off[i] += g_bsum[i >> 10];
}

// scatter bumps g_off in place: afterwards g_off[w] = orig + deg[w]
__global__ void scatter_k(const int* __restrict__ ei, int E)
{
    int e = blockIdx.x * blockDim.x + threadIdx.x;
    if (e >= E) return;
    int dst = ei[E + e];
    int pos = atomicAdd(&g_off[dst], 1);
    g_csr[pos] = ei[e];
}

// ---------------- fused aggregation: m = relu(p + sum_csr p[src] + b1) -------
// output written in packed hi/lo planes
__global__ void agg_fused(const float* __restrict__ p, const float* __restrict__ b,
                          uint32_t* __restrict__ out, int n)
{
    int w    = (blockIdx.x * blockDim.x + threadIdx.x) >> 5;
    int lane = threadIdx.x & 31;
    if (w >= n) return;
    int deg = g_deg[w];
    int off = g_off[w] - deg;          // g_off holds end after scatter
    const float* pc = p + (size_t)lane * 4;
    float4 acc = *(const float4*)&pc[(size_t)w * 128];

    for (int base = 0; base < deg; base += 32) {
        int idx = 0;
        if (base + lane < deg) idx = g_csr[off + base + lane];
        int cnt = min(32, deg - base);
        int j = 0;
        for (; j + 4 <= cnt; j += 4) {
            int s0 = __shfl_sync(0xffffffffu, idx, j);
            int s1 = __shfl_sync(0xffffffffu, idx, j + 1);
            int s2 = __shfl_sync(0xffffffffu, idx, j + 2);
            int s3 = __shfl_sync(0xffffffffu, idx, j + 3);
            float4 v0 = *(const float4*)&pc[(size_t)s0 * 128];
            float4 v1 = *(const float4*)&pc[(size_t)s1 * 128];
            float4 v2 = *(const float4*)&pc[(size_t)s2 * 128];
            float4 v3 = *(const float4*)&pc[(size_t)s3 * 128];
            acc.x += v0.x + v1.x + v2.x + v3.x;
            acc.y += v0.y + v1.y + v2.y + v3.y;
            acc.z += v0.z + v1.z + v2.z + v3.z;
            acc.w += v0.w + v1.w + v2.w + v3.w;
        }
        for (; j < cnt; j++) {
            int s = __shfl_sync(0xffffffffu, idx, j);
            float4 v = *(const float4*)&pc[(size_t)s * 128];
            acc.x += v.x; acc.y += v.y; acc.z += v.z; acc.w += v.w;
        }
    }
    float4 bv = *(const float4*)&b[lane * 4];
    float4 o;
    o.x = fmaxf(acc.x + bv.x, 0.f);
    o.y = fmaxf(acc.y + bv.y, 0.f);
    o.z = fmaxf(acc.z + bv.z, 0.f);
    o.w = fmaxf(acc.w + bv.w, 0.f);
    size_t wi = (size_t)w * 64 + 2 * lane;
    *(uint2*)&out[wi]          = make_uint2(hi_pair(o.x, o.y), hi_pair(o.z, o.w));
    *(uint2*)&out[NPLANE + wi] = make_uint2(lo_pair(o.x, o.y), lo_pair(o.z, o.w));
}

// ---------------- BN coefficients from stats (per layer); resets state -------
__global__ void bn_coef(const float* __restrict__ gamma, const float* __restrict__ beta,
                        int n, int l)
{
    int c = threadIdx.x;
    float s = g_stats[c], q = g_stats[128 + c];
    g_stats[c] = 0.f; g_stats[128 + c] = 0.f;   // ready for next layer / replay
    g_brow[c]  = 0.f;                            // ready for wfold accumulation
    float invn = 1.0f / (float)n;
    float mu   = s * invn;
    float var  = q * invn - mu * mu;
    float rstd = rsqrtf(var + BN_EPS);
    float sc   = gamma[c] * rstd;
    g_scale2[l * 128 + c] = sc;
    g_shift2[l * 128 + c] = beta[c] - mu * sc;
}

// ---------------- final head (linear-pool BN correction) + state cleanup -----
__global__ void final_mlp(const float* __restrict__ Wl1, const float* __restrict__ bl1,
                          const float* __restrict__ Wl2, const float* __restrict__ bl2,
                          float* __restrict__ out, int n)
{
    int g = blockIdx.x, tid = threadIdx.x;
    __shared__ float pooled[384];
    float cntv = g_cnt[g];
    float ic   = 1.0f / fmaxf(cntv, 1.0f);
    float have = cntv * ic;
    for (int i = tid; i < 384; i += 128) {
        pooled[i] = g_pool[(size_t)g * 384 + i] * g_scale2[i] * ic + g_shift2[i] * have;
        g_pool[(size_t)g * 384 + i] = 0.f;      // reset for next replay
    }
    __syncthreads();
    if (tid == 0) g_cnt[g] = 0.f;               // all threads read cntv pre-sync
    for (int i = g * 128 + tid; i < n; i += MAXG * 128)
        g_deg[i] = 0;                           // reset degrees for next replay
    float a = bl1[tid];
    #pragma unroll 4
    for (int k = 0; k < 384; k++)
        a = fmaf(pooled[k], Wl1[k * 128 + tid], a);
    float v = fmaxf(a, 0.f) * Wl2[tid];
    #pragma unroll
    for (int o = 16; o; o >>= 1) v += __shfl_xor_sync(0xffffffffu, v, o);
    __shared__ float ws[4];
    if ((tid & 31) == 0) ws[tid >> 5] = v;
    __syncthreads();
    if (tid == 0) out[g] = ws[0] + ws[1] + ws[2] + ws[3] + bl2[0];
}

// -----------------------------------------------------------------------------
extern "C" void kernel_launch(void* const* d_in, const int* in_sizes, int n_in,
                              void* d_out, int out_size)
{
    const float* x     = (const float*)d_in[0];
    const int*   z     = (const int*)  d_in[1];
    const int*   ei    = (const int*)  d_in[2];
    const int*   batch = (const int*)  d_in[3];
    const float *W1[3], *b1[3], *W2[3], *b2[3], *ga[3], *be[3];
    for (int l = 0; l < 3; l++) {
        W1[l] = (const float*)d_in[4 + 6 * l];
        b1[l] = (const float*)d_in[5 + 6 * l];
        W2[l] = (const float*)d_in[6 + 6 * l];
        b2[l] = (const float*)d_in[7 + 6 * l];
        ga[l] = (const float*)d_in[8 + 6 * l];
        be[l] = (const float*)d_in[9 + 6 * l];
    }
    const float* Wl1 = (const float*)d_in[22];
    const float* bl1 = (const float*)d_in[23];
    const float* Wl2 = (const float*)d_in[24];
    const float* bl2 = (const float*)d_in[25];
    float* out = (float*)d_out;

    int n = in_sizes[0] / 128;
    int E = in_sizes[2] / 2;
    int G = out_size;

    float *p_h, *p_pool, *p_scale2, *p_shift2, *p_brow;
    uint32_t *p_m, *p_p;
    cudaGetSymbolAddress((void**)&p_h,      g_h);
    cudaGetSymbolAddress((void**)&p_m,      g_m);
    cudaGetSymbolAddress((void**)&p_p,      g_p);
    cudaGetSymbolAddress((void**)&p_pool,   g_pool);
    cudaGetSymbolAddress((void**)&p_scale2, g_scale2);
    cudaGetSymbolAddress((void**)&p_shift2, g_shift2);
    cudaGetSymbolAddress((void**)&p_brow,   g_brow);

    cudaFuncSetAttribute(gemm_mma, cudaFuncAttributeMaxDynamicSharedMemorySize, SMEM_BYTES);

    int    gb    = (n + 127) / 128;
    size_t tot32 = (size_t)n * 32;
    int    nb32  = (int)((tot32 + 255) / 256);
    int    nb_scan = (n + 1023) / 1024;

    // ---- setup (no memsets: device globals start zero; kernels re-zero) -----
    hist_count_k<<<(E + 255) / 256, 256>>>(ei, batch, E, n);
    prep_k<<<98, 256>>>(W1[0] + 200 * 128, W2[0], W1[1], W2[1],
                        W1[2], W2[2], W1[0]);

    // layer-0 GEMM1: p = x @ W1_0[200:] + embsum[z]  (fp32 A path, fp32 out)
    gemm_mma<<<gb, 256, SMEM_BYTES>>>(x, nullptr, 0, nullptr, z, 1,
                                      p_h, nullptr, 0, n, 0, 0,
                                      nullptr, nullptr, 0, 0);

    scan1_k  <<<nb_scan, 1024>>>(n);
    scan2_k  <<<1, 256>>>(nb_scan);
    scan3_k  <<<(n + 255) / 256, 256>>>(n);
    scatter_k<<<(E + 255) / 256, 256>>>(ei, E);

    for (int l = 0; l < 3; l++) {
        // m = relu(p + sum_csr p[src] + b1)  -> packed planes
        agg_fused<<<nb32, 256>>>(p_h, b1[l], p_m, n);

        // t = relu(m @ W2 + b2): packed A in, stats + pool; packed t out (l<2)
        gemm_mma<<<gb, 256, SMEM_BYTES>>>(nullptr, p_m, 2 * l + 1, b2[l],
                                          nullptr, 0,
                                          nullptr, p_p, (l < 2) ? 1 : 2,
                                          n, 1, 1,
                                          batch, p_pool, l * 128, 1);

        // BN coefficients (also zeroes stats + brow)
        bn_coef<<<1, 128>>>(ga[l], be[l], n, l);

        if (l < 2) {
            // fold BN affine into next layer's W1: slot 2(l+1); brow = sh@W1
            wfold_k<<<32, 256>>>(W1[l + 1], p_scale2 + l * 128,
                                 p_shift2 + l * 128, 2 * (l + 1));
            // p = t @ W1eff + brow  (packed A in, fp32 out for aggregation)
            gemm_mma<<<gb, 256, SMEM_BYTES>>>(nullptr, p_p, 2 * (l + 1), p_brow,
                                              nullptr, 0,
                                              p_h, nullptr, 0, n, 0, 0,
                                              nullptr, nullptr, 0, 0);
        }
    }

    final_mlp<<<G, 128>>>(Wl1, bl1, Wl2, bl2, out, n);
}

// round 14
// speedup vs baseline: 1.5939x; 1.2552x over previous
#include <cuda_runtime.h>
#include <cuda_bf16.h>
#include <cstdint>

#define MAXN 100000
#define MAXE 1600000
#define MAXG 512
#define BN_EPS 1e-5f
#define NPLANE ((size_t)MAXN * 64)

// ---------------- scratch (static device globals; no allocations) ------------
__device__ float    g_h [(size_t)MAXN * 128];   // fp32 p (GEMM1 out, agg in)
__device__ uint32_t g_m [(size_t)MAXN * 128];   // packed m planes (agg out)
__device__ uint32_t g_p [(size_t)MAXN * 128];   // packed t planes (GEMM2 out)
__device__ float g_pool[(size_t)MAXG * 384];
__device__ float g_cnt [MAXG];
__device__ float g_stats[256];
__device__ float g_scale2[384];
__device__ float g_shift2[384];
__device__ float g_emb [100 * 128];
__device__ float g_brow[128];
// packed weights: layout word (kh, c) at kh*136 + c  (kh pairs rows 2kh,2kh+1)
#define WS2 136
#define W_PLANE (64 * WS2)
__device__ uint32_t g_wpack[6][2][W_PLANE];
// CSR scratch
__device__ int g_deg [MAXN];
__device__ int g_off [MAXN];
__device__ int g_bsum[256];
__device__ int g_csr [MAXE];

// smem: Ahi[128][68], Alo[128][68], Whi[64][136], Wlo[64][136]
#define AS2 68
#define A_PLANE (128 * AS2)
#define SMEM_BYTES ((2 * A_PLANE + 2 * W_PLANE) * 4)   // 139264

// pair two consecutive-k values into one b16x2 word (low = even k)
__device__ __forceinline__ uint32_t hi_pair(float a, float b)
{
    return (__float_as_uint(a) >> 16) | (__float_as_uint(b) & 0xFFFF0000u);
}
__device__ __forceinline__ uint32_t lo_pair(float a, float b)
{
    float ra = a - __uint_as_float(__float_as_uint(a) & 0xFFFF0000u);
    float rb = b - __uint_as_float(__float_as_uint(b) & 0xFFFF0000u);
    uint32_t la = (uint32_t)__bfloat16_as_ushort(__float2bfloat16(ra));
    uint32_t lb = (uint32_t)__bfloat16_as_ushort(__float2bfloat16(rb));
    return la | (lb << 16);
}

__device__ __forceinline__ void mma_bf16(float c[4], const uint32_t a[4], const uint32_t b[2])
{
    asm volatile(
        "mma.sync.aligned.m16n8k16.row.col.f32.bf16.bf16.f32 "
        "{%0,%1,%2,%3}, {%4,%5,%6,%7}, {%8,%9}, {%0,%1,%2,%3};"
        : "+f"(c[0]), "+f"(c[1]), "+f"(c[2]), "+f"(c[3])
        : "r"(a[0]), "r"(a[1]), "r"(a[2]), "r"(a[3]), "r"(b[0]), "r"(b[1]));
}

// ---------------- bf16x3 tensor-core GEMM: 128x128 tile, 512 threads ---------
// 16 warps (4 M x 4 N, 32x32 per warp), 1 CTA/SM -> 4 warps/SMSP.
// A: fp32 (packs inline) or pre-packed planes (straight copy).
// out_mode: 0 = fp32 store, 1 = packed store, 2 = no store.
__global__ void __launch_bounds__(512, 1)
gemm_mma(const float* __restrict__ A, const uint32_t* __restrict__ Apack, int widx,
         const float* __restrict__ bias, const int* __restrict__ z, int do_emb,
         float* __restrict__ outf, uint32_t* __restrict__ outp, int out_mode,
         int n, int do_relu, int do_stats,
         const int* __restrict__ batch, float* __restrict__ pool, int loff, int do_pool)
{
    extern __shared__ uint32_t sh[];
    uint32_t* Ahi = sh;
    uint32_t* Alo = sh + A_PLANE;
    uint32_t* Whi = sh + 2 * A_PLANE;
    uint32_t* Wlo = sh + 2 * A_PLANE + W_PLANE;
    const int tid  = threadIdx.x;            // 512
    const int row0 = blockIdx.x * 128;

    // stage W: straight uint4 copy of pre-packed planes
    {
        const uint4* src = (const uint4*)&g_wpack[widx][0][0];
        uint4* dst = (uint4*)Whi;
        for (int i = tid; i < (2 * W_PLANE) / 4; i += 512)
            dst[i] = src[i];
    }
    // stage A
    if (Apack) {
        for (int i = tid; i < 4096; i += 512) {
            int r  = i >> 5;                  // 0..127
            int jw = (i & 31) * 2;            // word pair index 0..62
            int row = row0 + r;
            uint2 hv = make_uint2(0u, 0u), lv = make_uint2(0u, 0u);
            if (row < n) {
                hv = *(const uint2*)&Apack[(size_t)row * 64 + jw];
                lv = *(const uint2*)&Apack[NPLANE + (size_t)row * 64 + jw];
            }
            *(uint2*)&Ahi[r * AS2 + jw] = hv;
            *(uint2*)&Alo[r * AS2 + jw] = lv;
        }
    } else {
        for (int i = tid; i < 4096; i += 512) {
            int r  = i >> 5;
            int c4 = (i & 31) * 4;
            int row = row0 + r;
            float4 v = make_float4(0.f, 0.f, 0.f, 0.f);
            if (row < n) v = *(const float4*)&A[(size_t)row * 128 + c4];
            uint2 hv, lv;
            hv.x = hi_pair(v.x, v.y); lv.x = lo_pair(v.x, v.y);
            hv.y = hi_pair(v.z, v.w); lv.y = lo_pair(v.z, v.w);
            *(uint2*)&Ahi[r * AS2 + (c4 >> 1)] = hv;
            *(uint2*)&Alo[r * AS2 + (c4 >> 1)] = lv;
        }
    }
    __syncthreads();

    const int w    = tid >> 5;           // 0..15
    const int lane = tid & 31;
    const int wm0  = (w & 3) * 32;       // 4 warps in M (32 rows each)
    const int n0   = (w >> 2) * 32;      // 4 warps in N (32 cols each)
    const int g    = lane >> 2;
    const int t    = lane & 3;

    float c[2][4][4];
    #pragma unroll
    for (int mt = 0; mt < 2; mt++)
        #pragma unroll
        for (int nt = 0; nt < 4; nt++)
            #pragma unroll
            for (int j = 0; j < 4; j++) c[mt][nt][j] = 0.f;

    #pragma unroll
    for (int kc = 0; kc < 8; kc++) {
        int kh16 = kc * 8;
        uint32_t ahi[2][4], alo[2][4];
        #pragma unroll
        for (int mt = 0; mt < 2; mt++) {
            int base = (wm0 + mt * 16 + g) * AS2 + kh16 + t;
            ahi[mt][0] = Ahi[base];
            ahi[mt][1] = Ahi[base + 8 * AS2];
            ahi[mt][2] = Ahi[base + 4];
            ahi[mt][3] = Ahi[base + 4 + 8 * AS2];
            alo[mt][0] = Alo[base];
            alo[mt][1] = Alo[base + 8 * AS2];
            alo[mt][2] = Alo[base + 4];
            alo[mt][3] = Alo[base + 4 + 8 * AS2];
        }
        #pragma unroll
        for (int nt = 0; nt < 4; nt++) {
            int col = n0 + nt * 8 + g;
            int wb  = (kh16 + t) * WS2 + col;
            uint32_t bhi[2], blo[2];
            bhi[0] = Whi[wb];
            bhi[1] = Whi[wb + 4 * WS2];
            blo[0] = Wlo[wb];
            blo[1] = Wlo[wb + 4 * WS2];
            #pragma unroll
            for (int mt = 0; mt < 2; mt++) {
                mma_bf16(c[mt][nt], ahi[mt], bhi);   // hi*hi
                mma_bf16(c[mt][nt], ahi[mt], blo);   // hi*lo
                mma_bf16(c[mt][nt], alo[mt], bhi);   // lo*hi
            }
        }
    }

    // ---------------- epilogue ----------------
    float sst[8], qst[8];
    #pragma unroll
    for (int i = 0; i < 8; i++) { sst[i] = 0.f; qst[i] = 0.f; }

    #pragma unroll
    for (int mt = 0; mt < 2; mt++) {
        #pragma unroll
        for (int rr = 0; rr < 2; rr++) {
            int row = row0 + wm0 + mt * 16 + rr * 8 + g;
            bool valid = row < n;
            const float* er = nullptr;
            if (do_emb && valid) er = &g_emb[(size_t)z[row] * 128];
            float* prow = nullptr;
            if (do_pool && valid) prow = &pool[(size_t)batch[row] * 384 + loff];
            #pragma unroll
            for (int nt = 0; nt < 4; nt++) {
                int col0 = n0 + nt * 8 + 2 * t;
                float v0 = c[mt][nt][rr * 2 + 0];
                float v1 = c[mt][nt][rr * 2 + 1];
                if (bias) { v0 += bias[col0]; v1 += bias[col0 + 1]; }
                if (er)   { v0 += er[col0];   v1 += er[col0 + 1]; }
                if (do_relu) { v0 = fmaxf(v0, 0.f); v1 = fmaxf(v1, 0.f); }
                if (do_stats && valid) {
                    sst[nt * 2 + 0] += v0; qst[nt * 2 + 0] += v0 * v0;
                    sst[nt * 2 + 1] += v1; qst[nt * 2 + 1] += v1 * v1;
                }
                if (valid) {
                    if (out_mode == 0) {
                        *(float2*)&outf[(size_t)row * 128 + col0] = make_float2(v0, v1);
                    } else if (out_mode == 1) {
                        size_t wi = (size_t)row * 64 + (col0 >> 1);
                        outp[wi]          = hi_pair(v0, v1);
                        outp[NPLANE + wi] = lo_pair(v0, v1);
                    }
                    if (prow)
                        asm volatile("red.global.add.v2.f32 [%0], {%1,%2};"
                                     :: "l"(prow + col0), "f"(v0), "f"(v1) : "memory");
                }
            }
        }
    }

    if (do_stats) {
        #pragma unroll
        for (int i = 0; i < 8; i++) {
            #pragma unroll
            for (int msk = 4; msk < 32; msk <<= 1) {
                sst[i] += __shfl_xor_sync(0xffffffffu, sst[i], msk);
                qst[i] += __shfl_xor_sync(0xffffffffu, qst[i], msk);
            }
        }
        if (g == 0) {
            #pragma unroll
            for (int i = 0; i < 8; i++) {
                int col = n0 + (i >> 1) * 8 + 2 * t + (i & 1);
                atomicAdd(&g_stats[col], sst[i]);
                atomicAdd(&g_stats[128 + col], qst[i]);
            }
        }
    }
}

// ---------------- prep: embsum + pack all 6 weight matrices ------------------
// blocks 0..49 = embsum; 50..97 = pack (8 blocks per weight)
__global__ void prep_k(const float* __restrict__ W0, const float* __restrict__ W1,
                       const float* __restrict__ W2, const float* __restrict__ W3,
                       const float* __restrict__ W4, const float* __restrict__ W5,
                       const float* __restrict__ W1_0full)
{
    int b = blockIdx.x;
    if (b < 50) {
        int zi = b * 2 + (threadIdx.x >> 7);
        int c  = threadIdx.x & 127;
        g_emb[zi * 128 + c] = W1_0full[zi * 128 + c] + W1_0full[(100 + zi) * 128 + c];
        return;
    }
    int widx = (b - 50) >> 3;
    int blk  = (b - 50) & 7;
    const float* W = W0;
    if (widx == 1) W = W1; else if (widx == 2) W = W2;
    else if (widx == 3) W = W3; else if (widx == 4) W = W4;
    else if (widx == 5) W = W5;
    int i  = blk * 256 + threadIdx.x;    // 0..2047
    int kh = i >> 5;
    int c4 = (i & 31) * 4;
    float4 r0 = *(const float4*)&W[(2 * kh)     * 128 + c4];
    float4 r1 = *(const float4*)&W[(2 * kh + 1) * 128 + c4];
    uint4 hv, lv;
    hv.x = hi_pair(r0.x, r1.x); lv.x = lo_pair(r0.x, r1.x);
    hv.y = hi_pair(r0.y, r1.y); lv.y = lo_pair(r0.y, r1.y);
    hv.z = hi_pair(r0.z, r1.z); lv.z = lo_pair(r0.z, r1.z);
    hv.w = hi_pair(r0.w, r1.w); lv.w = lo_pair(r0.w, r1.w);
    *(uint4*)&g_wpack[widx][0][kh * WS2 + c4] = hv;
    *(uint4*)&g_wpack[widx][1][kh * WS2 + c4] = lv;
}

// ---------------- weight fold: W1eff = diag(sc)*W1, brow += sh@W1 ------------
__global__ void wfold_k(const float* __restrict__ W1n, const float* __restrict__ sc,
                        const float* __restrict__ shv, int slot)
{
    int idx = blockIdx.x * 256 + threadIdx.x;   // grid 32 -> 8192
    int kh = idx >> 7, c = idx & 127;
    float s0 = sc[2 * kh], s1 = sc[2 * kh + 1];
    float v0 = W1n[(2 * kh) * 128 + c];
    float v1 = W1n[(2 * kh + 1) * 128 + c];
    g_wpack[slot][0][kh * WS2 + c] = hi_pair(s0 * v0, s1 * v1);
    g_wpack[slot][1][kh * WS2 + c] = lo_pair(s0 * v0, s1 * v1);
    atomicAdd(&g_brow[c], shv[2 * kh] * v0 + shv[2 * kh + 1] * v1);
}

// ---------------- hist (edge degrees) + per-graph node counts ----------------
__global__ void hist_count_k(const int* __restrict__ ei, const int* __restrict__ batch,
                             int E, int n)
{
    int idx = blockIdx.x * blockDim.x + threadIdx.x;
    if (idx < E) atomicAdd(&g_deg[ei[E + idx]], 1);
    if (idx < n) atomicAdd(&g_cnt[batch[idx]], 1.0f);
}

// ---------------- CSR scans + scatter ----------------------------------------
__global__ void scan1_k(int n)
{
    __shared__ int s[1024];
    int t = threadIdx.x, i = blockIdx.x * 1024 + t;
    int v = (i < n) ? g_deg[i] : 0;
    s[t] = v;
    __syncthreads();
    #pragma unroll
    for (int d = 1; d < 1024; d <<= 1) {
        int x = (t >= d) ? s[t - d] : 0;
        __syncthreads();
        s[t] += x;
        __syncthreads();
    }
    if (i < n) g_off[i] = s[t] - v;
    if (t == 1023) g_bsum[blockIdx.x] = s[t];
}

__global__ void scan2_k(int nb)
{
    __shared__ int s[256];
    int t = threadIdx.x;
    int v = (t < nb) ? g_bsum[t] : 0;
    s[t] = v;
    __syncthreads();
    #pragma unroll
    for (int d = 1; d < 256; d <<= 1) {
        int x = (t >= d) ? s[t - d] : 0;
        __syncthreads();
        s[t] += x;
        __syncthreads();
    }
    if (t < nb) g_bsum[t] = s[t] - v;
}

__global__ void scan3_k(int n)
{
    int i = blockIdx.x * blockDim.x + threadIdx.x;
    if (i < n) g_off[i] += g_bsum[i >> 10];
}

// scatter bumps g_off in place: afterwards g_off[w] = orig + deg[w]
__global__ void scatter_k(const int* __restrict__ ei, int E)
{
    int e = blockIdx.x * blockDim.x + threadIdx.x;
    if (e >= E) return;
    int dst = ei[E + e];
    int pos = atomicAdd(&g_off[dst], 1);
    g_csr[pos] = ei[e];
}

// ---------------- fused aggregation: m = relu(p + sum_csr p[src] + b1) -------
// output written in packed hi/lo planes
__global__ void agg_fused(const float* __restrict__ p, const float* __restrict__ b,
                          uint32_t* __restrict__ out, int n)
{
    int w    = (blockIdx.x * blockDim.x + threadIdx.x) >> 5;
    int lane = threadIdx.x & 31;
    if (w >= n) return;
    int deg = g_deg[w];
    int off = g_off[w] - deg;          // g_off holds end after scatter
    const float* pc = p + (size_t)lane * 4;
    float4 acc = *(const float4*)&pc[(size_t)w * 128];

    for (int base = 0; base < deg; base += 32) {
        int idx = 0;
        if (base + lane < deg) idx = g_csr[off + base + lane];
        int cnt = min(32, deg - base);
        int j = 0;
        for (; j + 4 <= cnt; j += 4) {
            int s0 = __shfl_sync(0xffffffffu, idx, j);
            int s1 = __shfl_sync(0xffffffffu, idx, j + 1);
            int s2 = __shfl_sync(0xffffffffu, idx, j + 2);
            int s3 = __shfl_sync(0xffffffffu, idx, j + 3);
            float4 v0 = *(const float4*)&pc[(size_t)s0 * 128];
            float4 v1 = *(const float4*)&pc[(size_t)s1 * 128];
            float4 v2 = *(const float4*)&pc[(size_t)s2 * 128];
            float4 v3 = *(const float4*)&pc[(size_t)s3 * 128];
            acc.x += v0.x + v1.x + v2.x + v3.x;
            acc.y += v0.y + v1.y + v2.y + v3.y;
            acc.z += v0.z + v1.z + v2.z + v3.z;
            acc.w += v0.w + v1.w + v2.w + v3.w;
        }
        for (; j < cnt; j++) {
            int s = __shfl_sync(0xffffffffu, idx, j);
            float4 v = *(const float4*)&pc[(size_t)s * 128];
            acc.x += v.x; acc.y += v.y; acc.z += v.z; acc.w += v.w;
        }
    }
    float4 bv = *(const float4*)&b[lane * 4];
    float4 o;
    o.x = fmaxf(acc.x + bv.x, 0.f);
    o.y = fmaxf(acc.y + bv.y, 0.f);
    o.z = fmaxf(acc.z + bv.z, 0.f);
    o.w = fmaxf(acc.w + bv.w, 0.f);
    size_t wi = (size_t)w * 64 + 2 * lane;
    *(uint2*)&out[wi]          = make_uint2(hi_pair(o.x, o.y), hi_pair(o.z, o.w));
    *(uint2*)&out[NPLANE + wi] = make_uint2(lo_pair(o.x, o.y), lo_pair(o.z, o.w));
}

// ---------------- BN coefficients from stats (per layer); resets state -------
__global__ void bn_coef(const float* __restrict__ gamma, const float* __restrict__ beta,
                        int n, int l)
{
    int c = threadIdx.x;
    float s = g_stats[c], q = g_stats[128 + c];
    g_stats[c] = 0.f; g_stats[128 + c] = 0.f;   // ready for next layer / replay
    g_brow[c]  = 0.f;                            // ready for wfold accumulation
    float invn = 1.0f / (float)n;
    float mu   = s * invn;
    float var  = q * invn - mu * mu;
    float rstd = rsqrtf(var + BN_EPS);
    float sc   = gamma[c] * rstd;
    g_scale2[l * 128 + c] = sc;
    g_shift2[l * 128 + c] = beta[c] - mu * sc;
}

// ---------------- final head (linear-pool BN correction) + state cleanup -----
__global__ void final_mlp(const float* __restrict__ Wl1, const float* __restrict__ bl1,
                          const float* __restrict__ Wl2, const float* __restrict__ bl2,
                          float* __restrict__ out, int n)
{
    int g = blockIdx.x, tid = threadIdx.x;
    __shared__ float pooled[384];
    float cntv = g_cnt[g];
    float ic   = 1.0f / fmaxf(cntv, 1.0f);
    float have = cntv * ic;
    for (int i = tid; i < 384; i += 128) {
        pooled[i] = g_pool[(size_t)g * 384 + i] * g_scale2[i] * ic + g_shift2[i] * have;
        g_pool[(size_t)g * 384 + i] = 0.f;      // reset for next replay
    }
    __syncthreads();
    if (tid == 0) g_cnt[g] = 0.f;               // all threads read cntv pre-sync
    for (int i = g * 128 + tid; i < n; i += MAXG * 128)
        g_deg[i] = 0;                           // reset degrees for next replay
    float a = bl1[tid];
    #pragma unroll 4
    for (int k = 0; k < 384; k++)
        a = fmaf(pooled[k], Wl1[k * 128 + tid], a);
    float v = fmaxf(a, 0.f) * Wl2[tid];
    #pragma unroll
    for (int o = 16; o; o >>= 1) v += __shfl_xor_sync(0xffffffffu, v, o);
    __shared__ float ws[4];
    if ((tid & 31) == 0) ws[tid >> 5] = v;
    __syncthreads();
    if (tid == 0) out[g] = ws[0] + ws[1] + ws[2] + ws[3] + bl2[0];
}

// -----------------------------------------------------------------------------
extern "C" void kernel_launch(void* const* d_in, const int* in_sizes, int n_in,
                              void* d_out, int out_size)
{
    const float* x     = (const float*)d_in[0];
    const int*   z     = (const int*)  d_in[1];
    const int*   ei    = (const int*)  d_in[2];
    const int*   batch = (const int*)  d_in[3];
    const float *W1[3], *b1[3], *W2[3], *b2[3], *ga[3], *be[3];
    for (int l = 0; l < 3; l++) {
        W1[l] = (const float*)d_in[4 + 6 * l];
        b1[l] = (const float*)d_in[5 + 6 * l];
        W2[l] = (const float*)d_in[6 + 6 * l];
        b2[l] = (const float*)d_in[7 + 6 * l];
        ga[l] = (const float*)d_in[8 + 6 * l];
        be[l] = (const float*)d_in[9 + 6 * l];
    }
    const float* Wl1 = (const float*)d_in[22];
    const float* bl1 = (const float*)d_in[23];
    const float* Wl2 = (const float*)d_in[24];
    const float* bl2 = (const float*)d_in[25];
    float* out = (float*)d_out;

    int n = in_sizes[0] / 128;
    int E = in_sizes[2] / 2;
    int G = out_size;

    float *p_h, *p_pool, *p_scale2, *p_shift2, *p_brow;
    uint32_t *p_m, *p_p;
    cudaGetSymbolAddress((void**)&p_h,      g_h);
    cudaGetSymbolAddress((void**)&p_m,      g_m);
    cudaGetSymbolAddress((void**)&p_p,      g_p);
    cudaGetSymbolAddress((void**)&p_pool,   g_pool);
    cudaGetSymbolAddress((void**)&p_scale2, g_scale2);
    cudaGetSymbolAddress((void**)&p_shift2, g_shift2);
    cudaGetSymbolAddress((void**)&p_brow,   g_brow);

    cudaFuncSetAttribute(gemm_mma, cudaFuncAttributeMaxDynamicSharedMemorySize, SMEM_BYTES);

    int    gb    = (n + 127) / 128;
    size_t tot32 = (size_t)n * 32;
    int    nb32  = (int)((tot32 + 255) / 256);
    int    nb_scan = (n + 1023) / 1024;

    // ---- setup (no memsets: device globals start zero; kernels re-zero) -----
    hist_count_k<<<(E + 255) / 256, 256>>>(ei, batch, E, n);
    prep_k<<<98, 256>>>(W1[0] + 200 * 128, W2[0], W1[1], W2[1],
                        W1[2], W2[2], W1[0]);

    // layer-0 GEMM1: p = x @ W1_0[200:] + embsum[z]  (fp32 A path, fp32 out)
    gemm_mma<<<gb, 512, SMEM_BYTES>>>(x, nullptr, 0, nullptr, z, 1,
                                      p_h, nullptr, 0, n, 0, 0,
                                      nullptr, nullptr, 0, 0);

    scan1_k  <<<nb_scan, 1024>>>(n);
    scan2_k  <<<1, 256>>>(nb_scan);
    scan3_k  <<<(n + 255) / 256, 256>>>(n);
    scatter_k<<<(E + 255) / 256, 256>>>(ei, E);

    for (int l = 0; l < 3; l++) {
        // m = relu(p + sum_csr p[src] + b1)  -> packed planes
        agg_fused<<<nb32, 256>>>(p_h, b1[l], p_m, n);

        // t = relu(m @ W2 + b2): packed A in, stats + pool; packed t out (l<2)
        gemm_mma<<<gb, 512, SMEM_BYTES>>>(nullptr, p_m, 2 * l + 1, b2[l],
                                          nullptr, 0,
                                          nullptr, p_p, (l < 2) ? 1 : 2,
                                          n, 1, 1,
                                          batch, p_pool, l * 128, 1);

        // BN coefficients (also zeroes stats + brow)
        bn_coef<<<1, 128>>>(ga[l], be[l], n, l);

        if (l < 2) {
            // fold BN affine into next layer's W1: slot 2(l+1); brow = sh@W1
            wfold_k<<<32, 256>>>(W1[l + 1], p_scale2 + l * 128,
                                 p_shift2 + l * 128, 2 * (l + 1));
            // p = t @ W1eff + brow  (packed A in, fp32 out for aggregation)
            gemm_mma<<<gb, 512, SMEM_BYTES>>>(nullptr, p_p, 2 * (l + 1), p_brow,
                                              nullptr, 0,
                                              p_h, nullptr, 0, n, 0, 0,
                                              nullptr, nullptr, 0, 0);
        }
    }

    final_mlp<<<G, 128>>>(Wl1, bl1, Wl2, bl2, out, n);
}